// round 9
// baseline (speedup 1.0000x reference)
#include <cuda_runtime.h>
#include <math.h>
#include <stdint.h>

#define EPSV 1e-5f
typedef unsigned long long ull;

// ---------------- f32x2 helpers ---------------------------------------------
static __device__ __forceinline__ ull pk2(float lo, float hi) {
    ull r; asm("mov.b64 %0,{%1,%2};" : "=l"(r) : "f"(lo), "f"(hi)); return r;
}
static __device__ __forceinline__ void upk2(ull v, float& lo, float& hi) {
    asm("mov.b64 {%0,%1},%2;" : "=f"(lo), "=f"(hi) : "l"(v));
}
static __device__ __forceinline__ ull f2fma(ull a, ull b, ull c) {
    ull r; asm("fma.rn.f32x2 %0,%1,%2,%3;" : "=l"(r) : "l"(a), "l"(b), "l"(c)); return r;
}
static __device__ __forceinline__ ull f2add(ull a, ull b) {
    ull r; asm("add.rn.f32x2 %0,%1,%2;" : "=l"(r) : "l"(a), "l"(b)); return r;
}

// ---------------- scratch ----------------------------------------------------
__device__ float g_xt[1 * 16 * 16 * 1024];
__device__ float g_h1[16 * 14 * 14 * 1024];
__device__ float g_h2[32 * 12 * 12 * 1024];
__device__ float g_h3[64 * 10 * 10 * 1024];          // pre-BN (BN3 fused in FC)
__device__ float g_stats[224];
__device__ float g_part[25 * 10 * 1024];
// transposed weights: T[loc][o][k], k = c*9+ij
__device__ float g_w1t[196 * 16 * 9];
__device__ float g_w2t[144 * 32 * 144];
__device__ float g_w3t[100 * 64 * 288];

// ---------------- fused prep: transpose x + zero stats + weight reorder -----
__global__ void prep_kernel(const float* __restrict__ x,
                            const float* __restrict__ W1,
                            const float* __restrict__ W2,
                            const float* __restrict__ W3) {
    int bid = blockIdx.x;
    if (bid < 256) {
        __shared__ float tile[32][33];
        int bx = bid % 8, by = bid / 8;
        int tx = threadIdx.x % 32, ty = threadIdx.x / 32;
        for (int r = 0; r < 4; r++) {
            int p = bx * 32 + tx;
            int b = by * 32 + ty + r * 8;
            tile[ty + r * 8][tx] = x[b * 256 + p];
        }
        __syncthreads();
        for (int r = 0; r < 4; r++) {
            int p2 = bx * 32 + ty + r * 8;
            int b2 = by * 32 + tx;
            g_xt[p2 * 1024 + b2] = tile[tx][ty + r * 8];
        }
        return;
    }
    if (bid == 256) {
        if (threadIdx.x < 224) g_stats[threadIdx.x] = 0.f;
        return;
    }
    long idx = (long)(bid - 257) * 256 + threadIdx.x;
    if (idx < 28224) {
        int k = idx % 9, o = (idx / 9) % 16, loc = idx / (9 * 16);
        g_w1t[idx] = W1[(((o * 1) * 14 + loc / 14) * 14 + loc % 14) * 9 + k];
        return;
    }
    idx -= 28224;
    if (idx < 663552) {
        int k = idx % 144, o = (idx / 144) % 32, loc = idx / (144 * 32);
        int c = k / 9, ij = k % 9;
        g_w2t[idx] = W2[((((o * 16 + c) * 12 + loc / 12) * 12 + loc % 12)) * 9 + ij];
        return;
    }
    idx -= 663552;
    if (idx < 1843200) {
        int k = idx % 288, o = (idx / 288) % 64, loc = idx / (288 * 64);
        int c = k / 9, ij = k % 9;
        g_w3t[idx] = W3[((((o * 32 + c) * 10 + loc / 10) * 10 + loc % 10)) * 9 + ij];
    }
}

// ---------------- locally-connected layer, round-5 mainloop + k-halved smem --
// in (C,HIN,HIN,1024) post-BN; WT[loc][o][k]; out (O_TOT,OH,OH,1024) pre-BN
// block (32,2): warp = 8 outputs x 256 batch (MB2=4)
// KH: number of staged k-halves (1 = round-5 behavior; 2 halves smem for LC3)
// grid (OH*OH, 4, O_TOT/16)
template <int C, int HIN, int OH, int O_TOT, int KH, int MINB>
__global__ void __launch_bounds__(64, MINB)
lc_kernel(const float* __restrict__ in, const float* __restrict__ WT,
          const float* __restrict__ bias, float* __restrict__ out,
          float* __restrict__ stats_out) {
    constexpr int KK   = C * 9;          // total k per output
    constexpr int CCH  = C / KH;         // channels per staged half
    constexpr int KKH  = CCH * 9;        // k per half
    constexpr int C10H = CCH * 10;       // padded k-extent in smem per half

    const int loc    = blockIdx.x;
    const int o_base = blockIdx.z * 16;
    const int lane   = threadIdx.x;
    const int b0     = blockIdx.y * 256 + lane * 2;
    const int tid    = threadIdx.y * 32 + lane;
    const int ogrp   = threadIdx.y;

    extern __shared__ __align__(16) unsigned char smraw[];
    ull* Ws2 = (ull*)smraw;              // [o(16)][cch][10] duplicated-packed

    ull acc[8][4];
#pragma unroll
    for (int o = 0; o < 8; o++)
#pragma unroll
        for (int m = 0; m < 4; m++) acc[o][m] = 0ull;

    const float* cp = in + ((size_t)(loc / OH) * HIN + (loc % OH)) * 1024 + b0;

#pragma unroll 1
    for (int h = 0; h < KH; h++) {
        // stage this k-half's weights (coalesced from WT)
        if (h > 0) __syncthreads();      // previous half's reads complete
        const float* wsrc = WT + ((size_t)loc * O_TOT + o_base) * KK + h * KKH;
        for (int lin = tid; lin < 16 * KKH; lin += 64) {
            int o = lin / KKH, k = lin - o * KKH;
            float w = wsrc[(size_t)o * KK + k];
            Ws2[o * C10H + (k / 9) * 10 + (k % 9)] = pk2(w, w);
        }
        __syncthreads();

        const ull* wp = Ws2 + ogrp * 8 * C10H;
#pragma unroll 1
        for (int c = 0; c < CCH; c++) {
#pragma unroll
            for (int p = 0; p < 4; p++) {
                const int ij0 = 2 * p, ij1 = 2 * p + 1;
                const int off0 = ((ij0 / 3) * HIN + (ij0 % 3)) * 1024;
                const int off1 = ((ij1 / 3) * HIN + (ij1 % 3)) * 1024;
                ull v0[4], v1[4];
#pragma unroll
                for (int m = 0; m < 4; m++) v0[m] = *(const ull*)(cp + off0 + 64 * m);
#pragma unroll
                for (int m = 0; m < 4; m++) v1[m] = *(const ull*)(cp + off1 + 64 * m);
#pragma unroll
                for (int o = 0; o < 8; o++) {
                    ulonglong2 w = *(const ulonglong2*)&wp[o * C10H + c * 10 + 2 * p];
#pragma unroll
                    for (int m = 0; m < 4; m++) acc[o][m] = f2fma(v0[m], w.x, acc[o][m]);
#pragma unroll
                    for (int m = 0; m < 4; m++) acc[o][m] = f2fma(v1[m], w.y, acc[o][m]);
                }
            }
            {   // singleton ij = 8 (i=2, j=2)
                const int off = (2 * HIN + 2) * 1024;
                ull v[4];
#pragma unroll
                for (int m = 0; m < 4; m++) v[m] = *(const ull*)(cp + off + 64 * m);
#pragma unroll
                for (int o = 0; o < 8; o++) {
                    ull w2 = wp[o * C10H + c * 10 + 8];
#pragma unroll
                    for (int m = 0; m < 4; m++) acc[o][m] = f2fma(v[m], w2, acc[o][m]);
                }
            }
            cp += HIN * HIN * 1024;
        }
    }

    // bias + store pre-BN + per-channel BN stats
#pragma unroll
    for (int o = 0; o < 8; o++) {
        int og = o_base + ogrp * 8 + o;
        float bb = __ldg(&bias[og * OH * OH + loc]);
        ull b2 = pk2(bb, bb);
        float* op = out + ((size_t)og * OH * OH + loc) * 1024 + b0;
        ull s2 = 0ull, q2 = 0ull;
#pragma unroll
        for (int m = 0; m < 4; m++) {
            ull r = f2add(acc[o][m], b2);
            *(ull*)(op + 64 * m) = r;
            s2 = f2add(s2, r);
            q2 = f2fma(r, r, q2);
        }
        float sl, sh, ql, qh;
        upk2(s2, sl, sh); upk2(q2, ql, qh);
        float s = sl + sh, q = ql + qh;
#pragma unroll
        for (int off = 16; off > 0; off >>= 1) {
            s += __shfl_down_sync(0xffffffffu, s, off);
            q += __shfl_down_sync(0xffffffffu, q, off);
        }
        if (lane == 0) {
            atomicAdd(&stats_out[og * 2 + 0], s);
            atomicAdd(&stats_out[og * 2 + 1], q);
        }
    }
}

// ---------------- BN apply + ReLU, in place ----------------------------------
__global__ void bn_relu_kernel(const float* __restrict__ stats, const float* __restrict__ g,
                               const float* __restrict__ be, float* __restrict__ data,
                               int per_chan, float inv_n) {
    int ch = blockIdx.y;
    float m  = stats[ch * 2 + 0] * inv_n;
    float v  = stats[ch * 2 + 1] * inv_n - m * m;
    float sc = g[ch] * rsqrtf(v + EPSV);
    float sh = be[ch] - sc * m;
    float4* p = (float4*)(data + (size_t)ch * per_chan);
    int i = blockIdx.x * blockDim.x + threadIdx.x;
    float4 t = p[i];
    t.x = fmaxf(fmaf(t.x, sc, sh), 0.f);
    t.y = fmaxf(fmaf(t.y, sc, sh), 0.f);
    t.z = fmaxf(fmaf(t.z, sc, sh), 0.f);
    t.w = fmaxf(fmaf(t.w, sc, sh), 0.f);
    p[i] = t;
}

// ---------------- FC with fused BN3 + tanh -----------------------------------
__global__ void fc_partial_kernel(const float* __restrict__ h, const float* __restrict__ Wfc,
                                  const float* __restrict__ stats, const float* __restrict__ g,
                                  const float* __restrict__ be, float inv_n) {
    const int FCH = 256;
    int b  = blockIdx.x * 128 + threadIdx.x;
    int f0 = blockIdx.y * FCH;
    __shared__ float Wsm[10 * FCH];
    __shared__ float fsc[FCH], fsh[FCH];
    for (int i = threadIdx.x; i < 10 * FCH; i += 128) {
        int t = i / FCH, f = i % FCH;
        Wsm[i] = Wfc[t * 6400 + f0 + f];
    }
    for (int f = threadIdx.x; f < FCH; f += 128) {
        int ch = (f0 + f) / 100;
        float m  = stats[ch * 2 + 0] * inv_n;
        float v  = stats[ch * 2 + 1] * inv_n - m * m;
        float sc = g[ch] * rsqrtf(v + EPSV);
        fsc[f] = sc;
        fsh[f] = be[ch] - sc * m;
    }
    __syncthreads();
    float acc[10];
#pragma unroll
    for (int t = 0; t < 10; t++) acc[t] = 0.f;
    for (int f = 0; f < FCH; f++) {
        float v = h[(size_t)(f0 + f) * 1024 + b];
        v = tanhf(fmaf(v, fsc[f], fsh[f]));
#pragma unroll
        for (int t = 0; t < 10; t++) acc[t] = fmaf(v, Wsm[t * FCH + f], acc[t]);
    }
#pragma unroll
    for (int t = 0; t < 10; t++)
        g_part[((size_t)blockIdx.y * 10 + t) * 1024 + b] = acc[t];
}

__global__ void fc_reduce_kernel(const float* __restrict__ fcb, float* __restrict__ out) {
    int idx = blockIdx.x * blockDim.x + threadIdx.x;
    if (idx >= 10240) return;
    int b = idx / 10, t = idx % 10;
    float s = fcb[t];
#pragma unroll
    for (int c = 0; c < 25; c++) s += g_part[((size_t)c * 10 + t) * 1024 + b];
    out[b * 10 + t] = s;
}

// ---------------- launch -----------------------------------------------------
extern "C" void kernel_launch(void* const* d_in, const int* in_sizes, int n_in,
                              void* d_out, int out_size) {
    const float* x   = (const float*)d_in[0];
    const float* W1  = (const float*)d_in[1];
    const float* b1  = (const float*)d_in[2];
    const float* g1  = (const float*)d_in[3];
    const float* be1 = (const float*)d_in[4];
    const float* W2  = (const float*)d_in[5];
    const float* b2  = (const float*)d_in[6];
    const float* g2  = (const float*)d_in[7];
    const float* be2 = (const float*)d_in[8];
    const float* W3  = (const float*)d_in[9];
    const float* b3  = (const float*)d_in[10];
    const float* g3  = (const float*)d_in[11];
    const float* be3 = (const float*)d_in[12];
    const float* fcW = (const float*)d_in[13];
    const float* fcb = (const float*)d_in[14];
    float* out = (float*)d_out;

    float *p_xt, *p_h1, *p_h2, *p_h3, *p_stats, *p_w1t, *p_w2t, *p_w3t;
    cudaGetSymbolAddress((void**)&p_xt, g_xt);
    cudaGetSymbolAddress((void**)&p_h1, g_h1);
    cudaGetSymbolAddress((void**)&p_h2, g_h2);
    cudaGetSymbolAddress((void**)&p_h3, g_h3);
    cudaGetSymbolAddress((void**)&p_stats, g_stats);
    cudaGetSymbolAddress((void**)&p_w1t, g_w1t);
    cudaGetSymbolAddress((void**)&p_w2t, g_w2t);
    cudaGetSymbolAddress((void**)&p_w3t, g_w3t);

    // smem: 16 outputs * (C/KH)*10 padded k-slots * 8B
    const int sm1 = 16 * 1 * 10 * 8;      // 1.28 KB (KH=1)
    const int sm2 = 16 * 16 * 10 * 8;     // 20.5 KB (KH=1)
    const int sm3 = 16 * 16 * 10 * 8;     // 20.5 KB (KH=2: 16 of 32 channels staged)
    cudaFuncSetAttribute((const void*)lc_kernel<1, 16, 14, 16, 1, 8>,
                         cudaFuncAttributeMaxDynamicSharedMemorySize, sm1);
    cudaFuncSetAttribute((const void*)lc_kernel<16, 14, 12, 32, 1, 8>,
                         cudaFuncAttributeMaxDynamicSharedMemorySize, sm2);
    cudaFuncSetAttribute((const void*)lc_kernel<32, 12, 10, 64, 2, 8>,
                         cudaFuncAttributeMaxDynamicSharedMemorySize, sm3);

    int wblocks = 257 + (28224 + 663552 + 1843200 + 255) / 256;
    prep_kernel<<<wblocks, 256>>>(x, W1, W2, W3);

    // #1 LC1, #2 bn1, #3 LC2 (profiled slot — control, expect ~54us)
    lc_kernel<1, 16, 14, 16, 1, 8><<<dim3(196, 4, 1), dim3(32, 2), sm1>>>(
        p_xt, p_w1t, b1, p_h1, p_stats + 0);
    bn_relu_kernel<<<dim3(196, 16), 256>>>(p_stats + 0, g1, be1, p_h1,
                                           14 * 14 * 1024, 1.f / (14.f * 14.f * 1024.f));
    lc_kernel<16, 14, 12, 32, 1, 8><<<dim3(144, 4, 2), dim3(32, 2), sm2>>>(
        p_h1, p_w2t, b2, p_h2, p_stats + 32);
    bn_relu_kernel<<<dim3(144, 32), 256>>>(p_stats + 32, g2, be2, p_h2,
                                           12 * 12 * 1024, 1.f / (12.f * 12.f * 1024.f));
    // LC3: KH=2 halves smem -> 8 blocks/SM (reg-bound) instead of 5 (smem-bound)
    lc_kernel<32, 12, 10, 64, 2, 8><<<dim3(100, 4, 4), dim3(32, 2), sm3>>>(
        p_h2, p_w3t, b3, p_h3, p_stats + 96);

    fc_partial_kernel<<<dim3(8, 25), 128>>>(p_h3, fcW, p_stats + 96, g3, be3,
                                            1.f / (10.f * 10.f * 1024.f));
    fc_reduce_kernel<<<40, 256>>>(fcb, out);
}

// round 10
// speedup vs baseline: 1.0062x; 1.0062x over previous
#include <cuda_runtime.h>
#include <math.h>
#include <stdint.h>

#define EPSV 1e-5f
typedef unsigned long long ull;

// ---------------- f32x2 helpers ---------------------------------------------
static __device__ __forceinline__ ull pk2(float lo, float hi) {
    ull r; asm("mov.b64 %0,{%1,%2};" : "=l"(r) : "f"(lo), "f"(hi)); return r;
}
static __device__ __forceinline__ void upk2(ull v, float& lo, float& hi) {
    asm("mov.b64 {%0,%1},%2;" : "=f"(lo), "=f"(hi) : "l"(v));
}
static __device__ __forceinline__ ull f2fma(ull a, ull b, ull c) {
    ull r; asm("fma.rn.f32x2 %0,%1,%2,%3;" : "=l"(r) : "l"(a), "l"(b), "l"(c)); return r;
}
static __device__ __forceinline__ ull f2add(ull a, ull b) {
    ull r; asm("add.rn.f32x2 %0,%1,%2;" : "=l"(r) : "l"(a), "l"(b)); return r;
}

// ---------------- scratch ----------------------------------------------------
__device__ float g_xt[1 * 16 * 16 * 1024];
__device__ float g_h1[16 * 14 * 14 * 1024];
__device__ float g_h2[32 * 12 * 12 * 1024];
__device__ float g_h3[64 * 10 * 10 * 1024];          // pre-BN (BN3 fused in FC)
__device__ float g_stats[224];
__device__ float g_part[25 * 10 * 1024];
// pre-packed weights {w,w} in padded layout [loc][o][c*10+ij] (slot 9 unused)
__device__ ull g_w1p[196 * 16 * 10];                 //   250 KB
__device__ ull g_w2p[144 * 32 * 160];                //   5.9 MB
__device__ ull g_w3p[100 * 64 * 320];                //  16.4 MB

// ---------------- fused prep: transpose x + zero stats + weight pack ---------
__global__ void prep_kernel(const float* __restrict__ x,
                            const float* __restrict__ W1,
                            const float* __restrict__ W2,
                            const float* __restrict__ W3) {
    int bid = blockIdx.x;
    if (bid < 256) {
        __shared__ float tile[32][33];
        int bx = bid % 8, by = bid / 8;
        int tx = threadIdx.x % 32, ty = threadIdx.x / 32;
        for (int r = 0; r < 4; r++) {
            int p = bx * 32 + tx;
            int b = by * 32 + ty + r * 8;
            tile[ty + r * 8][tx] = x[b * 256 + p];
        }
        __syncthreads();
        for (int r = 0; r < 4; r++) {
            int p2 = bx * 32 + ty + r * 8;
            int b2 = by * 32 + tx;
            g_xt[p2 * 1024 + b2] = tile[tx][ty + r * 8];
        }
        return;
    }
    if (bid == 256) {
        if (threadIdx.x < 224) g_stats[threadIdx.x] = 0.f;
        return;
    }
    long idx = (long)(bid - 257) * 256 + threadIdx.x;
    // layer 1: 196 loc * 16 o * 9 k
    if (idx < 28224) {
        int k = idx % 9, o = (idx / 9) % 16, loc = idx / 144;
        float w = W1[(((o * 1) * 14 + loc / 14) * 14 + loc % 14) * 9 + k];
        g_w1p[(loc * 16 + o) * 10 + k] = pk2(w, w);
        return;
    }
    idx -= 28224;
    // layer 2: 144 loc * 32 o * 144 k
    if (idx < 663552) {
        int k2 = idx % 144, o = (idx / 144) % 32, loc = idx / 4608;
        int c = k2 / 9, ij = k2 % 9;
        float w = W2[((((o * 16 + c) * 12 + loc / 12) * 12 + loc % 12)) * 9 + ij];
        g_w2p[((size_t)(loc * 32 + o)) * 160 + c * 10 + ij] = pk2(w, w);
        return;
    }
    idx -= 663552;
    // layer 3: 100 loc * 64 o * 288 k
    if (idx < 1843200) {
        int k3 = idx % 288, o = (idx / 288) % 64, loc = idx / 18432;
        int c = k3 / 9, ij = k3 % 9;
        float w = W3[((((o * 32 + c) * 10 + loc / 10) * 10 + loc % 10)) * 9 + ij];
        g_w3p[((size_t)(loc * 64 + o)) * 320 + c * 10 + ij] = pk2(w, w);
    }
}

// ---------------- locally-connected layer ------------------------------------
// in (C,HIN,HIN,1024) post-BN; WP[loc][o][C*10] packed; out (O_TOT,OH,OH,1024)
// block (32,2): warp = 8 outputs x 256 batch (MB2=4)
// KH: staged k-halves. grid (OH*OH, 4, O_TOT/16)
template <int C, int HIN, int OH, int O_TOT, int KH, int MINB>
__global__ void __launch_bounds__(64, MINB)
lc_kernel(const float* __restrict__ in, const ull* __restrict__ WP,
          const float* __restrict__ bias, float* __restrict__ out,
          float* __restrict__ stats_out) {
    constexpr int C10  = C * 10;         // packed k-extent per o (full)
    constexpr int CCH  = C / KH;         // channels per staged half
    constexpr int C10H = CCH * 10;       // packed k-extent per half

    const int loc    = blockIdx.x;
    const int o_base = blockIdx.z * 16;
    const int lane   = threadIdx.x;
    const int b0     = blockIdx.y * 256 + lane * 2;
    const int tid    = threadIdx.y * 32 + lane;
    const int ogrp   = threadIdx.y;

    extern __shared__ __align__(16) unsigned char smraw[];
    ull* Ws2 = (ull*)smraw;              // [o(16)][cch][10] packed

    ull acc[8][4];
#pragma unroll
    for (int o = 0; o < 8; o++)
#pragma unroll
        for (int m = 0; m < 4; m++) acc[o][m] = 0ull;

    const float* cp = in + ((size_t)(loc / OH) * HIN + (loc % OH)) * 1024 + b0;

#pragma unroll 1
    for (int h = 0; h < KH; h++) {
        if (h > 0) __syncthreads();      // previous half's reads complete
        // pure strided ull copy of this half's packed weights
        const ull* wsrc = WP + ((size_t)(loc * O_TOT + o_base)) * C10 + h * C10H;
        for (int lin = tid; lin < 16 * C10H; lin += 64) {
            int o = lin / C10H, kk = lin - o * C10H;
            Ws2[lin] = wsrc[(size_t)o * C10 + kk];
        }
        __syncthreads();

        const ull* wp = Ws2 + ogrp * 8 * C10H;
#pragma unroll 2
        for (int c = 0; c < CCH; c++) {
#pragma unroll
            for (int p = 0; p < 4; p++) {
                const int ij0 = 2 * p, ij1 = 2 * p + 1;
                const int off0 = ((ij0 / 3) * HIN + (ij0 % 3)) * 1024;
                const int off1 = ((ij1 / 3) * HIN + (ij1 % 3)) * 1024;
                ull v0[4], v1[4];
#pragma unroll
                for (int m = 0; m < 4; m++) v0[m] = *(const ull*)(cp + off0 + 64 * m);
#pragma unroll
                for (int m = 0; m < 4; m++) v1[m] = *(const ull*)(cp + off1 + 64 * m);
#pragma unroll
                for (int o = 0; o < 8; o++) {
                    ulonglong2 w = *(const ulonglong2*)&wp[o * C10H + c * 10 + 2 * p];
#pragma unroll
                    for (int m = 0; m < 4; m++) acc[o][m] = f2fma(v0[m], w.x, acc[o][m]);
#pragma unroll
                    for (int m = 0; m < 4; m++) acc[o][m] = f2fma(v1[m], w.y, acc[o][m]);
                }
            }
            {   // singleton ij = 8 (i=2, j=2)
                const int off = (2 * HIN + 2) * 1024;
                ull v[4];
#pragma unroll
                for (int m = 0; m < 4; m++) v[m] = *(const ull*)(cp + off + 64 * m);
#pragma unroll
                for (int o = 0; o < 8; o++) {
                    ull w2 = wp[o * C10H + c * 10 + 8];
#pragma unroll
                    for (int m = 0; m < 4; m++) acc[o][m] = f2fma(v[m], w2, acc[o][m]);
                }
            }
            cp += HIN * HIN * 1024;
        }
    }

    // bias + store pre-BN + per-channel BN stats
#pragma unroll
    for (int o = 0; o < 8; o++) {
        int og = o_base + ogrp * 8 + o;
        float bb = __ldg(&bias[og * OH * OH + loc]);
        ull b2 = pk2(bb, bb);
        float* op = out + ((size_t)og * OH * OH + loc) * 1024 + b0;
        ull s2 = 0ull, q2 = 0ull;
#pragma unroll
        for (int m = 0; m < 4; m++) {
            ull r = f2add(acc[o][m], b2);
            *(ull*)(op + 64 * m) = r;
            s2 = f2add(s2, r);
            q2 = f2fma(r, r, q2);
        }
        float sl, sh, ql, qh;
        upk2(s2, sl, sh); upk2(q2, ql, qh);
        float s = sl + sh, q = ql + qh;
#pragma unroll
        for (int off = 16; off > 0; off >>= 1) {
            s += __shfl_down_sync(0xffffffffu, s, off);
            q += __shfl_down_sync(0xffffffffu, q, off);
        }
        if (lane == 0) {
            atomicAdd(&stats_out[og * 2 + 0], s);
            atomicAdd(&stats_out[og * 2 + 1], q);
        }
    }
}

// ---------------- BN apply + ReLU, in place ----------------------------------
__global__ void bn_relu_kernel(const float* __restrict__ stats, const float* __restrict__ g,
                               const float* __restrict__ be, float* __restrict__ data,
                               int per_chan, float inv_n) {
    int ch = blockIdx.y;
    float m  = stats[ch * 2 + 0] * inv_n;
    float v  = stats[ch * 2 + 1] * inv_n - m * m;
    float sc = g[ch] * rsqrtf(v + EPSV);
    float sh = be[ch] - sc * m;
    float4* p = (float4*)(data + (size_t)ch * per_chan);
    int i = blockIdx.x * blockDim.x + threadIdx.x;
    float4 t = p[i];
    t.x = fmaxf(fmaf(t.x, sc, sh), 0.f);
    t.y = fmaxf(fmaf(t.y, sc, sh), 0.f);
    t.z = fmaxf(fmaf(t.z, sc, sh), 0.f);
    t.w = fmaxf(fmaf(t.w, sc, sh), 0.f);
    p[i] = t;
}

// ---------------- FC with fused BN3 + tanh -----------------------------------
__global__ void fc_partial_kernel(const float* __restrict__ h, const float* __restrict__ Wfc,
                                  const float* __restrict__ stats, const float* __restrict__ g,
                                  const float* __restrict__ be, float inv_n) {
    const int FCH = 256;
    int b  = blockIdx.x * 128 + threadIdx.x;
    int f0 = blockIdx.y * FCH;
    __shared__ float Wsm[10 * FCH];
    __shared__ float fsc[FCH], fsh[FCH];
    for (int i = threadIdx.x; i < 10 * FCH; i += 128) {
        int t = i / FCH, f = i % FCH;
        Wsm[i] = Wfc[t * 6400 + f0 + f];
    }
    for (int f = threadIdx.x; f < FCH; f += 128) {
        int ch = (f0 + f) / 100;
        float m  = stats[ch * 2 + 0] * inv_n;
        float v  = stats[ch * 2 + 1] * inv_n - m * m;
        float sc = g[ch] * rsqrtf(v + EPSV);
        fsc[f] = sc;
        fsh[f] = be[ch] - sc * m;
    }
    __syncthreads();
    float acc[10];
#pragma unroll
    for (int t = 0; t < 10; t++) acc[t] = 0.f;
    for (int f = 0; f < FCH; f++) {
        float v = h[(size_t)(f0 + f) * 1024 + b];
        v = tanhf(fmaf(v, fsc[f], fsh[f]));
#pragma unroll
        for (int t = 0; t < 10; t++) acc[t] = fmaf(v, Wsm[t * FCH + f], acc[t]);
    }
#pragma unroll
    for (int t = 0; t < 10; t++)
        g_part[((size_t)blockIdx.y * 10 + t) * 1024 + b] = acc[t];
}

__global__ void fc_reduce_kernel(const float* __restrict__ fcb, float* __restrict__ out) {
    int idx = blockIdx.x * blockDim.x + threadIdx.x;
    if (idx >= 10240) return;
    int b = idx / 10, t = idx % 10;
    float s = fcb[t];
#pragma unroll
    for (int c = 0; c < 25; c++) s += g_part[((size_t)c * 10 + t) * 1024 + b];
    out[b * 10 + t] = s;
}

// ---------------- launch -----------------------------------------------------
extern "C" void kernel_launch(void* const* d_in, const int* in_sizes, int n_in,
                              void* d_out, int out_size) {
    const float* x   = (const float*)d_in[0];
    const float* W1  = (const float*)d_in[1];
    const float* b1  = (const float*)d_in[2];
    const float* g1  = (const float*)d_in[3];
    const float* be1 = (const float*)d_in[4];
    const float* W2  = (const float*)d_in[5];
    const float* b2  = (const float*)d_in[6];
    const float* g2  = (const float*)d_in[7];
    const float* be2 = (const float*)d_in[8];
    const float* W3  = (const float*)d_in[9];
    const float* b3  = (const float*)d_in[10];
    const float* g3  = (const float*)d_in[11];
    const float* be3 = (const float*)d_in[12];
    const float* fcW = (const float*)d_in[13];
    const float* fcb = (const float*)d_in[14];
    float* out = (float*)d_out;

    float *p_xt, *p_h1, *p_h2, *p_h3, *p_stats;
    ull *p_w1p, *p_w2p, *p_w3p;
    cudaGetSymbolAddress((void**)&p_xt, g_xt);
    cudaGetSymbolAddress((void**)&p_h1, g_h1);
    cudaGetSymbolAddress((void**)&p_h2, g_h2);
    cudaGetSymbolAddress((void**)&p_h3, g_h3);
    cudaGetSymbolAddress((void**)&p_stats, g_stats);
    cudaGetSymbolAddress((void**)&p_w1p, g_w1p);
    cudaGetSymbolAddress((void**)&p_w2p, g_w2p);
    cudaGetSymbolAddress((void**)&p_w3p, g_w3p);

    // smem: 16 outputs * (C/KH)*10 packed slots * 8B
    const int sm1 = 16 * 1 * 10 * 8;      // 1.28 KB (KH=1)
    const int sm2 = 16 * 16 * 10 * 8;     // 20.5 KB (KH=1)
    const int sm3 = 16 * 16 * 10 * 8;     // 20.5 KB (KH=2)
    cudaFuncSetAttribute((const void*)lc_kernel<1, 16, 14, 16, 1, 8>,
                         cudaFuncAttributeMaxDynamicSharedMemorySize, sm1);
    cudaFuncSetAttribute((const void*)lc_kernel<16, 14, 12, 32, 1, 6>,
                         cudaFuncAttributeMaxDynamicSharedMemorySize, sm2);
    cudaFuncSetAttribute((const void*)lc_kernel<32, 12, 10, 64, 2, 6>,
                         cudaFuncAttributeMaxDynamicSharedMemorySize, sm3);

    int wblocks = 257 + (28224 + 663552 + 1843200 + 255) / 256;
    prep_kernel<<<wblocks, 256>>>(x, W1, W2, W3);

    // #1 LC1, #2 bn1, #3 LC2 (profiled slot — watch regs & issue%)
    lc_kernel<1, 16, 14, 16, 1, 8><<<dim3(196, 4, 1), dim3(32, 2), sm1>>>(
        p_xt, p_w1p, b1, p_h1, p_stats + 0);
    bn_relu_kernel<<<dim3(196, 16), 256>>>(p_stats + 0, g1, be1, p_h1,
                                           14 * 14 * 1024, 1.f / (14.f * 14.f * 1024.f));
    lc_kernel<16, 14, 12, 32, 1, 6><<<dim3(144, 4, 2), dim3(32, 2), sm2>>>(
        p_h1, p_w2p, b2, p_h2, p_stats + 32);
    bn_relu_kernel<<<dim3(144, 32), 256>>>(p_stats + 32, g2, be2, p_h2,
                                           12 * 12 * 1024, 1.f / (12.f * 12.f * 1024.f));
    lc_kernel<32, 12, 10, 64, 2, 6><<<dim3(100, 4, 4), dim3(32, 2), sm3>>>(
        p_h2, p_w3p, b3, p_h3, p_stats + 96);

    fc_partial_kernel<<<dim3(8, 25), 128>>>(p_h3, fcW, p_stats + 96, g3, be3,
                                            1.f / (10.f * 10.f * 1024.f));
    fc_reduce_kernel<<<40, 256>>>(fcb, out);
}

// round 11
// speedup vs baseline: 1.7042x; 1.6937x over previous
#include <cuda_runtime.h>
#include <math.h>
#include <stdint.h>

#define EPSV 1e-5f
typedef unsigned long long ull;

// ---------------- helpers -----------------------------------------------------
static __device__ __forceinline__ ull pk2(float lo, float hi) {
    ull r; asm("mov.b64 %0,{%1,%2};" : "=l"(r) : "f"(lo), "f"(hi)); return r;
}
static __device__ __forceinline__ void upk2(ull v, float& lo, float& hi) {
    asm("mov.b64 {%0,%1},%2;" : "=f"(lo), "=f"(hi) : "l"(v));
}
static __device__ __forceinline__ ull f2fma(ull a, ull b, ull c) {
    ull r; asm("fma.rn.f32x2 %0,%1,%2,%3;" : "=l"(r) : "l"(a), "l"(b), "l"(c)); return r;
}
static __device__ __forceinline__ ull f2add(ull a, ull b) {
    ull r; asm("add.rn.f32x2 %0,%1,%2;" : "=l"(r) : "l"(a), "l"(b)); return r;
}
static __device__ __forceinline__ float tf32r(float v) {
    unsigned u; asm("cvt.rna.tf32.f32 %0, %1;" : "=r"(u) : "f"(v));
    return __uint_as_float(u);
}

// ---------------- scratch -----------------------------------------------------
__device__ float g_xt[1 * 16 * 16 * 1024];
__device__ float g_h1[16 * 14 * 14 * 1024];
__device__ float g_h2[32 * 12 * 12 * 1024];
__device__ float g_h3[64 * 10 * 10 * 1024];          // pre-BN (BN3 fused in FC)
__device__ float g_stats[224];
__device__ float g_part[25 * 10 * 1024];
__device__ ull   g_w1p[196 * 16 * 10];               // LC1 packed {w,w}
// tf32 fragment-ordered weights: idx = (((loc*OT+ot)*NSTEP+ks)*32+lane)*4+j
__device__ float g_w2f[144 * 2 * 18 * 32 * 4];       // 663552
__device__ float g_w3f[100 * 4 * 36 * 32 * 4];       // 1843200

// ---------------- fused prep: transpose + zero stats + weight pack ------------
__global__ void prep_kernel(const float* __restrict__ x,
                            const float* __restrict__ W1,
                            const float* __restrict__ W2,
                            const float* __restrict__ W3) {
    int bid = blockIdx.x;
    if (bid < 256) {
        __shared__ float tile[32][33];
        int bx = bid % 8, by = bid / 8;
        int tx = threadIdx.x % 32, ty = threadIdx.x / 32;
        for (int r = 0; r < 4; r++) {
            int p = bx * 32 + tx;
            int b = by * 32 + ty + r * 8;
            tile[ty + r * 8][tx] = x[b * 256 + p];
        }
        __syncthreads();
        for (int r = 0; r < 4; r++) {
            int p2 = bx * 32 + ty + r * 8;
            int b2 = by * 32 + tx;
            g_xt[p2 * 1024 + b2] = tile[tx][ty + r * 8];
        }
        return;
    }
    if (bid == 256) {
        if (threadIdx.x < 224) g_stats[threadIdx.x] = 0.f;
        return;
    }
    long idx = (long)(bid - 257) * 256 + threadIdx.x;
    // LC1: packed {w,w}, [loc][o][10]
    if (idx < 28224) {
        int k = idx % 9, o = (idx / 9) % 16, loc = idx / 144;
        float w = W1[(((o * 1) * 14 + loc / 14) * 14 + loc % 14) * 9 + k];
        g_w1p[(loc * 16 + o) * 10 + k] = pk2(w, w);
        return;
    }
    idx -= 28224;
    // LC2 tf32 fragments: OT=2, NSTEP=18
    if (idx < 663552) {
        int j = idx & 3, lane = (idx >> 2) & 31;
        int ks = (int)((idx >> 7) % 18);
        int ot = (int)((idx / (128 * 18)) & 1);
        int loc = (int)(idx / (128 * 18 * 2));
        int g = lane >> 2, tig = lane & 3;
        int o = ot * 16 + (j & 1) * 8 + g;
        int k = ks * 8 + tig + (j >> 1) * 4;
        int c = k / 9, ij = k % 9;
        float w = W2[((((o * 16 + c) * 12 + loc / 12) * 12 + loc % 12)) * 9 + ij];
        g_w2f[idx] = tf32r(w);
        return;
    }
    idx -= 663552;
    // LC3 tf32 fragments: OT=4, NSTEP=36
    if (idx < 1843200) {
        int j = idx & 3, lane = (idx >> 2) & 31;
        int ks = (int)((idx >> 7) % 36);
        int ot = (int)((idx / (128 * 36)) & 3);
        int loc = (int)(idx / 18432);
        int g = lane >> 2, tig = lane & 3;
        int o = ot * 16 + (j & 1) * 8 + g;
        int k = ks * 8 + tig + (j >> 1) * 4;
        int c = k / 9, ij = k % 9;
        float w = W3[((((o * 32 + c) * 10 + loc / 10) * 10 + loc % 10)) * 9 + ij];
        g_w3f[idx] = tf32r(w);
    }
}

// ---------------- LC1 (C=1): scalar f32x2 (round-5 proven) --------------------
__global__ void __launch_bounds__(64, 8)
lc1_kernel(const float* __restrict__ in, const ull* __restrict__ WP,
           const float* __restrict__ bias, float* __restrict__ out,
           float* __restrict__ stats_out) {
    const int OH = 14, HIN = 16;
    const int loc  = blockIdx.x;
    const int lane = threadIdx.x;
    const int b0   = blockIdx.y * 256 + lane * 2;
    const int tid  = threadIdx.y * 32 + lane;
    const int ogrp = threadIdx.y;

    __shared__ ull Ws2[16 * 10];
    const ull* wsrc = WP + (size_t)loc * 160;
    for (int lin = tid; lin < 160; lin += 64) Ws2[lin] = wsrc[lin];
    __syncthreads();

    ull acc[8][4];
#pragma unroll
    for (int o = 0; o < 8; o++)
#pragma unroll
        for (int m = 0; m < 4; m++) acc[o][m] = 0ull;

    const ull* wp = Ws2 + ogrp * 8 * 10;
    const float* cp = in + ((size_t)(loc / OH) * HIN + (loc % OH)) * 1024 + b0;

#pragma unroll
    for (int p = 0; p < 4; p++) {
        const int ij0 = 2 * p, ij1 = 2 * p + 1;
        const int off0 = ((ij0 / 3) * HIN + (ij0 % 3)) * 1024;
        const int off1 = ((ij1 / 3) * HIN + (ij1 % 3)) * 1024;
        ull v0[4], v1[4];
#pragma unroll
        for (int m = 0; m < 4; m++) v0[m] = *(const ull*)(cp + off0 + 64 * m);
#pragma unroll
        for (int m = 0; m < 4; m++) v1[m] = *(const ull*)(cp + off1 + 64 * m);
#pragma unroll
        for (int o = 0; o < 8; o++) {
            ulonglong2 w = *(const ulonglong2*)&wp[o * 10 + 2 * p];
#pragma unroll
            for (int m = 0; m < 4; m++) acc[o][m] = f2fma(v0[m], w.x, acc[o][m]);
#pragma unroll
            for (int m = 0; m < 4; m++) acc[o][m] = f2fma(v1[m], w.y, acc[o][m]);
        }
    }
    {
        const int off = (2 * HIN + 2) * 1024;
        ull v[4];
#pragma unroll
        for (int m = 0; m < 4; m++) v[m] = *(const ull*)(cp + off + 64 * m);
#pragma unroll
        for (int o = 0; o < 8; o++) {
            ull w2 = wp[o * 10 + 8];
#pragma unroll
            for (int m = 0; m < 4; m++) acc[o][m] = f2fma(v[m], w2, acc[o][m]);
        }
    }

#pragma unroll
    for (int o = 0; o < 8; o++) {
        int og = ogrp * 8 + o;
        float bb = __ldg(&bias[og * 196 + loc]);
        ull b2 = pk2(bb, bb);
        float* op = out + ((size_t)og * 196 + loc) * 1024 + b0;
        ull s2 = 0ull, q2 = 0ull;
#pragma unroll
        for (int m = 0; m < 4; m++) {
            ull r = f2add(acc[o][m], b2);
            *(ull*)(op + 64 * m) = r;
            s2 = f2add(s2, r);
            q2 = f2fma(r, r, q2);
        }
        float sl, sh, ql, qh;
        upk2(s2, sl, sh); upk2(q2, ql, qh);
        float s = sl + sh, q = ql + qh;
#pragma unroll
        for (int off = 16; off > 0; off >>= 1) {
            s += __shfl_down_sync(0xffffffffu, s, off);
            q += __shfl_down_sync(0xffffffffu, q, off);
        }
        if (lane == 0) {
            atomicAdd(&stats_out[og * 2 + 0], s);
            atomicAdd(&stats_out[og * 2 + 1], q);
        }
    }
}

// ---------------- tensor-core LC (tf32 mma.sync) ------------------------------
// D[o, b] = sum_k W[o,k] * X[k,b] per location.
// Block: NW=O_TOT/16 warps; warp w handles o-tile w (16 o) x 64 batch (8 n-tiles).
// Inputs staged 8 channels (72 k-rows x 64 batch) at a time, double-buffered cp.async.
// grid (OH*OH, 16)
template <int C, int HIN, int OH, int O_TOT>
__global__ void __launch_bounds__((O_TOT / 16) * 32, 5)
lc_tc_kernel(const float* __restrict__ in, const float* __restrict__ WF,
             const float* __restrict__ bias, float* __restrict__ out,
             float* __restrict__ stats_out) {
    constexpr int NW    = O_TOT / 16;
    constexpr int NTH   = NW * 32;
    constexpr int KK    = C * 9;
    constexpr int NSTEP = KK / 8;
    constexpr int NSTG  = C / 8;
    constexpr int RPS   = 72;     // k-rows per stage (8 channels)
    constexpr int BP    = 72;     // row pitch (floats) -> conflict-free LDS

    extern __shared__ __align__(16) unsigned char smraw[];
    float* buf  = (float*)smraw;                      // [2][RPS*BP]
    int* kbase  = (int*)(buf + 2 * RPS * BP);         // [KK]

    const int loc   = blockIdx.x, y = loc / OH, x = loc % OH;
    const int b_blk = blockIdx.y * 64;
    const int lane  = threadIdx.x, w = threadIdx.y;
    const int tid   = w * 32 + lane;
    const int g     = lane >> 2, tig = lane & 3;

    for (int k = tid; k < KK; k += NTH) {
        int c = k / 9, ij = k % 9;
        kbase[k] = ((c * HIN + y + ij / 3) * HIN + (x + ij % 3)) * 1024 + b_blk;
    }
    __syncthreads();

#define STAGE(ST) do { \
    const int _r0 = (ST) * RPS; \
    float* _db = buf + ((ST) & 1) * RPS * BP; \
    _Pragma("unroll") \
    for (int _it = 0; _it < RPS * 16 / NTH; _it++) { \
        int _t = tid + _it * NTH; \
        int _r = _t >> 4, _c = _t & 15; \
        const float* _src = in + kbase[_r0 + _r] + _c * 4; \
        unsigned _d = (unsigned)__cvta_generic_to_shared(_db + _r * BP + _c * 4); \
        asm volatile("cp.async.cg.shared.global [%0], [%1], 16;" :: "r"(_d), "l"(_src)); \
    } \
    asm volatile("cp.async.commit_group;"); } while (0)

    STAGE(0);

    float acc[8][4];
#pragma unroll
    for (int nt = 0; nt < 8; nt++)
#pragma unroll
        for (int j = 0; j < 4; j++) acc[nt][j] = 0.f;

    const float* wf = WF + ((size_t)(loc * NW + w) * NSTEP * 32 + lane) * 4;

#pragma unroll 1
    for (int st = 0; st < NSTG; st++) {
        asm volatile("cp.async.wait_group 0;");
        __syncthreads();
        if (st + 1 < NSTG) STAGE(st + 1);
        const float* bb = buf + (st & 1) * RPS * BP;
#pragma unroll
        for (int kl = 0; kl < 9; kl++) {
            const int ks = st * 9 + kl;
            float4 afv = *(const float4*)(wf + (size_t)ks * 128);
            unsigned a0 = __float_as_uint(afv.x), a1 = __float_as_uint(afv.y);
            unsigned a2 = __float_as_uint(afv.z), a3 = __float_as_uint(afv.w);
            const float* br0 = bb + (kl * 8 + tig) * BP + g;
            const float* br1 = br0 + 4 * BP;
#pragma unroll
            for (int nt = 0; nt < 8; nt++) {
                unsigned b0 = __float_as_uint(br0[nt * 8]);
                unsigned b1 = __float_as_uint(br1[nt * 8]);
                asm volatile(
                    "mma.sync.aligned.m16n8k8.row.col.f32.tf32.tf32.f32 "
                    "{%0,%1,%2,%3}, {%4,%5,%6,%7}, {%8,%9}, {%0,%1,%2,%3};"
                    : "+f"(acc[nt][0]), "+f"(acc[nt][1]),
                      "+f"(acc[nt][2]), "+f"(acc[nt][3])
                    : "r"(a0), "r"(a1), "r"(a2), "r"(a3), "r"(b0), "r"(b1));
            }
        }
    }
#undef STAGE

    // epilogue: bias + store pre-BN + BN stats
    const int olo = w * 16 + g, ohi = olo + 8;
    float blo = __ldg(&bias[olo * OH * OH + loc]);
    float bhi = __ldg(&bias[ohi * OH * OH + loc]);
    float* plo = out + ((size_t)olo * OH * OH + loc) * 1024 + b_blk + 2 * tig;
    float* phi = out + ((size_t)ohi * OH * OH + loc) * 1024 + b_blk + 2 * tig;
    float slo = 0.f, qlo = 0.f, shi = 0.f, qhi = 0.f;
#pragma unroll
    for (int nt = 0; nt < 8; nt++) {
        float d0 = acc[nt][0] + blo, d1 = acc[nt][1] + blo;
        float d2 = acc[nt][2] + bhi, d3 = acc[nt][3] + bhi;
        *(float2*)(plo + nt * 8) = make_float2(d0, d1);
        *(float2*)(phi + nt * 8) = make_float2(d2, d3);
        slo += d0 + d1; qlo += d0 * d0 + d1 * d1;
        shi += d2 + d3; qhi += d2 * d2 + d3 * d3;
    }
#pragma unroll
    for (int m = 1; m < 4; m <<= 1) {
        slo += __shfl_xor_sync(0xffffffffu, slo, m);
        qlo += __shfl_xor_sync(0xffffffffu, qlo, m);
        shi += __shfl_xor_sync(0xffffffffu, shi, m);
        qhi += __shfl_xor_sync(0xffffffffu, qhi, m);
    }
    if (tig == 0) {
        atomicAdd(&stats_out[olo * 2 + 0], slo);
        atomicAdd(&stats_out[olo * 2 + 1], qlo);
        atomicAdd(&stats_out[ohi * 2 + 0], shi);
        atomicAdd(&stats_out[ohi * 2 + 1], qhi);
    }
}

// ---------------- BN apply + ReLU (+tf32 round), in place ---------------------
template <int TF32R>
__global__ void bn_relu_kernel(const float* __restrict__ stats, const float* __restrict__ g,
                               const float* __restrict__ be, float* __restrict__ data,
                               int per_chan, float inv_n) {
    int ch = blockIdx.y;
    float m  = stats[ch * 2 + 0] * inv_n;
    float v  = stats[ch * 2 + 1] * inv_n - m * m;
    float sc = g[ch] * rsqrtf(v + EPSV);
    float sh = be[ch] - sc * m;
    float4* p = (float4*)(data + (size_t)ch * per_chan);
    int i = blockIdx.x * blockDim.x + threadIdx.x;
    float4 t = p[i];
    t.x = fmaxf(fmaf(t.x, sc, sh), 0.f);
    t.y = fmaxf(fmaf(t.y, sc, sh), 0.f);
    t.z = fmaxf(fmaf(t.z, sc, sh), 0.f);
    t.w = fmaxf(fmaf(t.w, sc, sh), 0.f);
    if (TF32R) { t.x = tf32r(t.x); t.y = tf32r(t.y); t.z = tf32r(t.z); t.w = tf32r(t.w); }
    p[i] = t;
}

// ---------------- FC with fused BN3 + tanh ------------------------------------
__global__ void fc_partial_kernel(const float* __restrict__ h, const float* __restrict__ Wfc,
                                  const float* __restrict__ stats, const float* __restrict__ g,
                                  const float* __restrict__ be, float inv_n) {
    const int FCH = 256;
    int b  = blockIdx.x * 128 + threadIdx.x;
    int f0 = blockIdx.y * FCH;
    __shared__ float Wsm[10 * FCH];
    __shared__ float fsc[FCH], fsh[FCH];
    for (int i = threadIdx.x; i < 10 * FCH; i += 128) {
        int t = i / FCH, f = i % FCH;
        Wsm[i] = Wfc[t * 6400 + f0 + f];
    }
    for (int f = threadIdx.x; f < FCH; f += 128) {
        int ch = (f0 + f) / 100;
        float m  = stats[ch * 2 + 0] * inv_n;
        float v  = stats[ch * 2 + 1] * inv_n - m * m;
        float sc = g[ch] * rsqrtf(v + EPSV);
        fsc[f] = sc;
        fsh[f] = be[ch] - sc * m;
    }
    __syncthreads();
    float acc[10];
#pragma unroll
    for (int t = 0; t < 10; t++) acc[t] = 0.f;
    for (int f = 0; f < FCH; f++) {
        float v = h[(size_t)(f0 + f) * 1024 + b];
        v = tanhf(fmaf(v, fsc[f], fsh[f]));
#pragma unroll
        for (int t = 0; t < 10; t++) acc[t] = fmaf(v, Wsm[t * FCH + f], acc[t]);
    }
#pragma unroll
    for (int t = 0; t < 10; t++)
        g_part[((size_t)blockIdx.y * 10 + t) * 1024 + b] = acc[t];
}

__global__ void fc_reduce_kernel(const float* __restrict__ fcb, float* __restrict__ out) {
    int idx = blockIdx.x * blockDim.x + threadIdx.x;
    if (idx >= 10240) return;
    int b = idx / 10, t = idx % 10;
    float s = fcb[t];
#pragma unroll
    for (int c = 0; c < 25; c++) s += g_part[((size_t)c * 10 + t) * 1024 + b];
    out[b * 10 + t] = s;
}

// ---------------- launch -------------------------------------------------------
extern "C" void kernel_launch(void* const* d_in, const int* in_sizes, int n_in,
                              void* d_out, int out_size) {
    const float* x   = (const float*)d_in[0];
    const float* W1  = (const float*)d_in[1];
    const float* b1  = (const float*)d_in[2];
    const float* g1  = (const float*)d_in[3];
    const float* be1 = (const float*)d_in[4];
    const float* W2  = (const float*)d_in[5];
    const float* b2  = (const float*)d_in[6];
    const float* g2  = (const float*)d_in[7];
    const float* be2 = (const float*)d_in[8];
    const float* W3  = (const float*)d_in[9];
    const float* b3  = (const float*)d_in[10];
    const float* g3  = (const float*)d_in[11];
    const float* be3 = (const float*)d_in[12];
    const float* fcW = (const float*)d_in[13];
    const float* fcb = (const float*)d_in[14];
    float* out = (float*)d_out;

    float *p_xt, *p_h1, *p_h2, *p_h3, *p_stats, *p_w2f, *p_w3f;
    ull* p_w1p;
    cudaGetSymbolAddress((void**)&p_xt, g_xt);
    cudaGetSymbolAddress((void**)&p_h1, g_h1);
    cudaGetSymbolAddress((void**)&p_h2, g_h2);
    cudaGetSymbolAddress((void**)&p_h3, g_h3);
    cudaGetSymbolAddress((void**)&p_stats, g_stats);
    cudaGetSymbolAddress((void**)&p_w1p, g_w1p);
    cudaGetSymbolAddress((void**)&p_w2f, g_w2f);
    cudaGetSymbolAddress((void**)&p_w3f, g_w3f);

    // dynamic smem: double input buffer + kbase table
    const int smt2 = 2 * 72 * 72 * 4 + 144 * 4;   // LC2: ~42.0 KB
    const int smt3 = 2 * 72 * 72 * 4 + 288 * 4;   // LC3: ~42.6 KB
    cudaFuncSetAttribute((const void*)lc_tc_kernel<16, 14, 12, 32>,
                         cudaFuncAttributeMaxDynamicSharedMemorySize, smt2);
    cudaFuncSetAttribute((const void*)lc_tc_kernel<32, 12, 10, 64>,
                         cudaFuncAttributeMaxDynamicSharedMemorySize, smt3);

    int wblocks = 257 + (28224 + 663552 + 1843200 + 255) / 256;
    prep_kernel<<<wblocks, 256>>>(x, W1, W2, W3);

    // #1 LC1, #2 bn1(tf32 round), #3 LC2-tensor (profiled slot)
    lc1_kernel<<<dim3(196, 4), dim3(32, 2)>>>(p_xt, p_w1p, b1, p_h1, p_stats + 0);
    bn_relu_kernel<1><<<dim3(196, 16), 256>>>(p_stats + 0, g1, be1, p_h1,
                                              14 * 14 * 1024, 1.f / (14.f * 14.f * 1024.f));
    lc_tc_kernel<16, 14, 12, 32><<<dim3(144, 16), dim3(32, 2), smt2>>>(
        p_h1, p_w2f, b2, p_h2, p_stats + 32);
    bn_relu_kernel<1><<<dim3(144, 32), 256>>>(p_stats + 32, g2, be2, p_h2,
                                              12 * 12 * 1024, 1.f / (12.f * 12.f * 1024.f));
    lc_tc_kernel<32, 12, 10, 64><<<dim3(100, 16), dim3(32, 4), smt3>>>(
        p_h2, p_w3f, b3, p_h3, p_stats + 96);

    fc_partial_kernel<<<dim3(8, 25), 128>>>(p_h3, fcW, p_stats + 96, g3, be3,
                                            1.f / (10.f * 10.f * 1024.f));
    fc_reduce_kernel<<<40, 256>>>(fcb, out);
}